// round 13
// baseline (speedup 1.0000x reference)
#include <cuda_runtime.h>

// EMA along T with geometric-decay chunking, round 12: warmup amortization.
// x: [B=8, T=4096, F=1024] fp32, y_t = 0.9*y_{t-1} + 0.1*x_t, y_{-1}=0.
//
// Champion (banked, 47.6us): CHUNK=256/LOOKBACK=64, 512x128, amp 1.25x.
// R12 experiment: each block runs 2 consecutive chunks T-sequentially with
// ONE 64-step warmup -> work/output 1.25x -> 1.125x (-10%). Cost: total
// warps halve to 1024 (~7/SM). R1 suggests that may starve BW, but R1 was
// confounded by an unbalanced 1.73-wave launch; this is a clean balanced
// 512-block x 64-thread grid with the proven per-warp codegen
// (float2 lanes, unroll 16, 48-reg shape, st.global.cs).
// Decision metric: achieved HBM GB/s vs champion's 5.84 TB/s.

#define T_DIM    4096
#define F_DIM    1024
#define B_DIM    8
#define SPAN     512            // outputs per block (2 old chunks)
#define LOOKBACK 64
#define ALPHA    0.9f
#define OMALPHA  0.1f

#define F2 (F_DIM / 2)          // 512 float2 lanes across features
#define NSPAN (T_DIM / SPAN)    // 8
#define BTHREADS 64

__device__ __forceinline__ void stcs2(float2* p, float2 v) {
    asm volatile("st.global.cs.v2.f32 [%0], {%1,%2};"
                 :: "l"(p), "f"(v.x), "f"(v.y) : "memory");
}

__global__ __launch_bounds__(BTHREADS, 16)
void ema_span_kernel(const float* __restrict__ x, float* __restrict__ y) {
    const int span = blockIdx.x;                               // 0..7 (fastest -> adjacent SMs)
    const int f2 = blockIdx.y * BTHREADS + threadIdx.x;        // 0..511
    const int b = blockIdx.z;                                  // 0..7

    const int t0 = span * SPAN;
    const int tw = (t0 >= LOOKBACK) ? (t0 - LOOKBACK) : 0;

    const float2* __restrict__ xp =
        reinterpret_cast<const float2*>(x) + (size_t)b * T_DIM * F2 + f2;
    float2* __restrict__ yp =
        reinterpret_cast<float2*>(y) + (size_t)b * T_DIM * F2 + f2;

    float ax = 0.f, ay = 0.f;

    // ---- warmup: reconstruct carry over [tw, t0) ----
    #pragma unroll 16
    for (int t = tw; t < t0; ++t) {
        float2 v = __ldg(&xp[(size_t)t * F2]);
        ax = fmaf(ALPHA, ax, OMALPHA * v.x);
        ay = fmaf(ALPHA, ay, OMALPHA * v.y);
    }

    // ---- main: produce outputs for [t0, t0+SPAN) ----
    #pragma unroll 16
    for (int i = 0; i < SPAN; ++i) {
        const int tt = t0 + i;
        float2 v = __ldg(&xp[(size_t)tt * F2]);
        ax = fmaf(ALPHA, ax, OMALPHA * v.x);
        ay = fmaf(ALPHA, ay, OMALPHA * v.y);
        float2 o; o.x = ax; o.y = ay;
        stcs2(&yp[(size_t)tt * F2], o);
    }
}

extern "C" void kernel_launch(void* const* d_in, const int* in_sizes, int n_in,
                              void* d_out, int out_size) {
    (void)in_sizes; (void)n_in; (void)out_size;
    const float* x = (const float*)d_in[0];
    float* y = (float*)d_out;

    dim3 block(BTHREADS, 1, 1);
    dim3 grid(NSPAN, F2 / BTHREADS, B_DIM);   // (8, 8, 8) = 512 blocks
    ema_span_kernel<<<grid, block>>>(x, y);
}

// round 14
// speedup vs baseline: 1.1290x; 1.1290x over previous
#include <cuda_runtime.h>

// EMA along T with geometric-decay chunking — FINAL.
// x: [B=8, T=4096, F=1024] fp32, y_t = 0.9*y_{t-1} + 0.1*x_t, y_{-1}=0.
// Each 256-step chunk reconstructs its carry via a 64-step warmup from 0;
// truncation bound 0.9^65 -> measured rel_err 1.477e-4, 6.8x under the gate.
//
// Design-space map (13 rounds of controlled experiments):
//  - DRAM bytes at the 268MB compulsory floor (lookback fully L2-deduped).
//  - Mixed-R/W HBM wall ~6.0TB/s, reachable only at >=14 warps/SM:
//      7 w/SM -> 4.9TB/s (R1, R12), 14-28 w/SM -> 6.0TB/s (R2-R7).
//  - Amp reduction below 1.25x requires either 7 w/SM (R12: -10% work,
//    -18% BW, net loss) or scalar lanes (R8: LSU throttle, net loss).
//  - Codegen sweet spot: float2 / unroll 16 / 48 regs / lb(128,8); any
//    deviation raised L1 replays and dropped DRAM% (R8, R9).
//  - LOOKBACK<64 gains are under the ~5% run noise and thin the margin.
// Best measured with this exact source: 47.6us (R11), 47.9us (R7);
// profiled 42.2-42.6us ~= roofline (268MB @ ~6TB/s x 1.25 warmup amp,
// overlapped).

#define T_DIM    4096
#define F_DIM    1024
#define B_DIM    8
#define CHUNK    256
#define LOOKBACK 64
#define ALPHA    0.9f
#define OMALPHA  0.1f

#define F2 (F_DIM / 2)          // 512 float2 lanes across features
#define NCHUNK (T_DIM / CHUNK)  // 16

__device__ __forceinline__ void stcs2(float2* p, float2 v) {
    asm volatile("st.global.cs.v2.f32 [%0], {%1,%2};"
                 :: "l"(p), "f"(v.x), "f"(v.y) : "memory");
}

__global__ __launch_bounds__(128, 8)
void ema_chunk_kernel(const float* __restrict__ x, float* __restrict__ y) {
    const int chunk = blockIdx.x;                             // 0..15 (fastest -> adjacent SMs)
    const int f2 = blockIdx.y * blockDim.x + threadIdx.x;     // 0..511
    const int b = blockIdx.z;                                 // 0..7

    const int t0 = chunk * CHUNK;
    const int tw = (t0 >= LOOKBACK) ? (t0 - LOOKBACK) : 0;

    const float2* __restrict__ xp =
        reinterpret_cast<const float2*>(x) + (size_t)b * T_DIM * F2 + f2;
    float2* __restrict__ yp =
        reinterpret_cast<float2*>(y) + (size_t)b * T_DIM * F2 + f2;

    float ax = 0.f, ay = 0.f;

    // ---- warmup: reconstruct carry over [tw, t0) ----
    #pragma unroll 16
    for (int t = tw; t < t0; ++t) {
        float2 v = __ldg(&xp[(size_t)t * F2]);
        ax = fmaf(ALPHA, ax, OMALPHA * v.x);
        ay = fmaf(ALPHA, ay, OMALPHA * v.y);
    }

    // ---- main: produce outputs for [t0, t0+CHUNK) ----
    #pragma unroll 16
    for (int i = 0; i < CHUNK; ++i) {
        const int tt = t0 + i;
        float2 v = __ldg(&xp[(size_t)tt * F2]);
        ax = fmaf(ALPHA, ax, OMALPHA * v.x);
        ay = fmaf(ALPHA, ay, OMALPHA * v.y);
        float2 o; o.x = ax; o.y = ay;
        stcs2(&yp[(size_t)tt * F2], o);
    }
}

extern "C" void kernel_launch(void* const* d_in, const int* in_sizes, int n_in,
                              void* d_out, int out_size) {
    (void)in_sizes; (void)n_in; (void)out_size;
    const float* x = (const float*)d_in[0];
    float* y = (float*)d_out;

    dim3 block(128, 1, 1);
    dim3 grid(NCHUNK, F2 / 128, B_DIM);   // (16, 4, 8) = 512 blocks
    ema_chunk_kernel<<<grid, block>>>(x, y);
}